// round 16
// baseline (speedup 1.0000x reference)
#include <cuda_runtime.h>
#include <cuda_fp16.h>
#include <math.h>
#include <stdint.h>

#define Bb 8
#define Ss 4096
#define Hn 512
#define Kd 512
#define Mtot (Bb*Ss)          // 32768
#define RYT 256               // row tiles (128 rows)
#define CXT 8                 // col tiles (64 cols)
#define NCHUNK 16             // K chunks of 32

// Tiled gmem images matching smem layout: 80B (40-half) padded rows.
#define ABLK_H 5120           // halves per (ry, chunk): 128 rows x 40
#define WBLK_H 2560           // halves per (mat, cx, chunk): 64 rows x 40

__device__ __align__(256) __half  g_x0[(size_t)RYT*NCHUNK*ABLK_H];
__device__ __align__(256) __half  g_xh[(size_t)RYT*NCHUNK*ABLK_H];
__device__ __align__(256) __half  g_w [(size_t)4*CXT*NCHUNK*WBLK_H];
__device__ __align__(256) float2  g_loc[2][RYT*Hn];
__device__ __align__(256) float   g_inc[2][RYT*Hn];
__device__ __align__(256) int     g_fl [2][RYT*CXT];
__device__ __align__(256) int     g_rdy[RYT];
__device__ int g_tick;

// ------------------------------ helpers ------------------------------------
__device__ __forceinline__ uint32_t s2u(const void* p) {
    uint32_t a;
    asm("{ .reg .u64 t; cvta.to.shared.u64 t, %1; cvt.u32.u64 %0, t; }"
        : "=r"(a) : "l"(p));
    return a;
}

__device__ __forceinline__ void mma_f16(float* d, const uint32_t* a,
                                        uint32_t b0, uint32_t b1) {
    asm volatile(
        "mma.sync.aligned.m16n8k16.row.col.f32.f16.f16.f32 "
        "{%0,%1,%2,%3}, {%4,%5,%6,%7}, {%8,%9}, {%0,%1,%2,%3};"
        : "+f"(d[0]), "+f"(d[1]), "+f"(d[2]), "+f"(d[3])
        : "r"(a[0]), "r"(a[1]), "r"(a[2]), "r"(a[3]), "r"(b0), "r"(b1));
}

__device__ __forceinline__ void ldsm4(uint32_t* r, uint32_t addr) {
    asm volatile("ldmatrix.sync.aligned.m8n8.x4.shared.b16 {%0,%1,%2,%3}, [%4];"
        : "=r"(r[0]), "=r"(r[1]), "=r"(r[2]), "=r"(r[3]) : "r"(addr));
}

__device__ __forceinline__ void mbar_init(uint32_t m, uint32_t cnt) {
    asm volatile("mbarrier.init.shared.b64 [%0], %1;" :: "r"(m), "r"(cnt) : "memory");
}
__device__ __forceinline__ void mbar_expect(uint32_t m, uint32_t bytes) {
    asm volatile("mbarrier.arrive.expect_tx.shared.b64 _, [%0], %1;"
                 :: "r"(m), "r"(bytes) : "memory");
}
__device__ __forceinline__ void mbar_arrive(uint32_t m) {
    asm volatile("mbarrier.arrive.shared.b64 _, [%0];" :: "r"(m) : "memory");
}
__device__ __forceinline__ void mbar_wait(uint32_t m, uint32_t parity) {
    asm volatile(
        "{\n\t.reg .pred P1;\n\t"
        "WL%=:\n\t"
        "mbarrier.try_wait.parity.acquire.cta.shared::cta.b64 P1, [%0], %1, 0x989680;\n\t"
        "@P1 bra.uni WD%=;\n\t"
        "bra.uni WL%=;\n\t"
        "WD%=:\n\t}"
        :: "r"(m), "r"(parity) : "memory");
}
__device__ __forceinline__ void bulkcp(uint32_t dst, const void* gsrc,
                                       uint32_t bytes, uint32_t mbar) {
    uint64_t ga;
    asm volatile("cvta.to.global.u64 %0, %1;" : "=l"(ga) : "l"(gsrc));
    asm volatile(
        "cp.async.bulk.shared::cluster.global.mbarrier::complete_tx::bytes "
        "[%0], [%1], %2, [%3];"
        :: "r"(dst), "l"(ga), "r"(bytes), "r"(mbar) : "memory");
}

// batched affine compose over predecessors pTop ... pTop-cnt+1
__device__ __forceinline__ void compose_n(int layer, int pTop, int cnt, int col,
                                          float& alpha, float& beta) {
    int l = 0;
    while (l + 8 <= cnt) {
        float2 buf[8];
#pragma unroll
        for (int j = 0; j < 8; j++)
            buf[j] = __ldcg(&g_loc[layer][(size_t)(pTop - l - j) * Hn + col]);
#pragma unroll
        for (int j = 0; j < 8; j++) {
            beta  = fmaf(alpha, buf[j].y, beta);
            alpha *= buf[j].x;
        }
        l += 8;
    }
    for (; l < cnt; l++) {
        float2 pv = __ldcg(&g_loc[layer][(size_t)(pTop - l) * Hn + col]);
        beta  = fmaf(alpha, pv.y, beta);
        alpha *= pv.x;
    }
}

// --------------------- merged setup: clear + conv x + conv w ----------------
#define CONVX_BLOCKS (Mtot*Kd/4/256)   // 16384
#define CONVW_BLOCKS (4*(Kd*Hn/4/256)) // 1024
#define CLR_BLOCKS 18
#define SETUP_BLOCKS (CONVX_BLOCKS + CONVW_BLOCKS + CLR_BLOCKS)

__global__ void setup_all(const float* __restrict__ x,
                          const float* __restrict__ w0, const float* __restrict__ w1,
                          const float* __restrict__ w2, const float* __restrict__ w3)
{
    const int bx = blockIdx.x;
    const int tid = threadIdx.x;

    if (bx < CONVX_BLOCKS) {
        int i = bx * 256 + tid;                   // over Mtot*Kd/4
        float4 v = ((const float4*)x)[i];
        __half2 p0 = __floats2half2_rn(v.x, v.y);
        __half2 p1 = __floats2half2_rn(v.z, v.w);
        const int m = i >> 7;
        const int k = (i & 127) * 4;
        const int ry = m >> 7, c = k >> 5, row = m & 127, col = k & 31;
        __half2* dst = (__half2*)&g_x0[(size_t)(ry * NCHUNK + c) * ABLK_H + row * 40 + col];
        dst[0] = p0; dst[1] = p1;
    } else if (bx < CONVX_BLOCKS + CONVW_BLOCKS) {
        const int b = bx - CONVX_BLOCKS;
        const float* srcs[4] = {w0, w1, w2, w3};
        const int mat = b >> 8;
        int i = (b & 255) * 256 + tid;            // over Kd*Hn/4
        float4 v = ((const float4*)srcs[mat])[i];
        __half2 p0 = __floats2half2_rn(v.x, v.y);
        __half2 p1 = __floats2half2_rn(v.z, v.w);
        const int h = i >> 7;
        const int k = (i & 127) * 4;
        const int cx = h >> 6, c = k >> 5, row = h & 63, col = k & 31;
        __half2* dst = (__half2*)&g_w[(size_t)(((mat * CXT + cx) * NCHUNK) + c) * WBLK_H
                                      + row * 40 + col];
        dst[0] = p0; dst[1] = p1;
    } else {
        int i = (bx - CONVX_BLOCKS - CONVW_BLOCKS) * 256 + tid;
        if (i < 2 * RYT * CXT) ((int*)g_fl)[i] = 0;
        else if (i < 2 * RYT * CXT + RYT) g_rdy[i - 2 * RYT * CXT] = 0;
        else if (i == 2 * RYT * CXT + RYT) g_tick = 0;
    }
}

// ---------------- fused dual GEMM + scan, BOTH layers in one kernel ---------
// smem: A slots 0..3 at 0 (4 x 10240), WZ slots at 40960 (4 x 5120),
// WH slots at 61440 (4 x 5120). Pipeline in PAIRS of chunks (2 pair-slots).
// Epilogue reuses smem as interleaved float2 (a,b) plane, stride 66.
#define SMEM_BYTES 81920
#define PAIR_BYTES 40960

__global__ __launch_bounds__(256, 2)
void gemm_scan(const float* __restrict__ bz0, const float* __restrict__ bh0,
               const float* __restrict__ bz1, const float* __restrict__ bh1,
               float* __restrict__ out, float* __restrict__ finalsBase)
{
    extern __shared__ __align__(16) char sm[];
    const uint32_t sb = s2u(sm);
    __shared__ __align__(8) uint64_t s_full[2];
    __shared__ __align__(8) uint64_t s_cons[2];
    __shared__ int s_tick, s_n[2], s_f2[2];

    const int tid  = threadIdx.x;
    const int lane = tid & 31;
    const int wid  = tid >> 5;
    const int gq   = lane >> 2;
    const int tq   = lane & 3;
    const int wm   = wid & 3;
    const int wn   = wid >> 2;
    const uint32_t mbF = s2u(s_full);
    const uint32_t mbC = s2u(s_cons);

    if (tid == 0) {
        s_tick = atomicAdd(&g_tick, 1);
#pragma unroll
        for (int s = 0; s < 2; s++) {
            mbar_init(mbF + 8 * s, 1);
            mbar_init(mbC + 8 * s, 8);
        }
    }
    __syncthreads();
    const int tk    = s_tick;
    const int layer = (tk >= RYT * CXT) ? 1 : 0;
    const int tk2   = tk & (RYT * CXT - 1);
    const int ry = tk2 >> 3;
    const int cx = tk2 & 7;
    const int rowBase = ry * 128;
    const int colBase = cx * 64;
    const int batchBase = ry & ~31;

    const float* bz = layer ? bz1 : bz0;
    const float* bh = layer ? bh1 : bh0;
    float* finals = finalsBase + layer * Bb * Hn;

    const __half* Ab  = (layer ? g_xh : g_x0) + (size_t)ry * NCHUNK * ABLK_H;
    const __half* Wzb = g_w + (size_t)((2 * layer)     * CXT + cx) * NCHUNK * WBLK_H;
    const __half* Whb = g_w + (size_t)((2 * layer + 1) * CXT + cx) * NCHUNK * WBLK_H;

    const uint32_t aLane = (uint32_t)((32 * wm + (lane & 15)) * 80 + ((lane >> 4) << 4));
    const uint32_t bLane = (uint32_t)(((32 * wn) + ((lane >> 4) << 3) + (lane & 7)) * 80
                                      + (((lane >> 3) & 1) << 4));

    float accZ[2][4][4];
    float accH[2][4][4];
#pragma unroll
    for (int mbi = 0; mbi < 2; mbi++)
#pragma unroll
        for (int nb = 0; nb < 4; nb++)
#pragma unroll
            for (int r = 0; r < 4; r++) { accZ[mbi][nb][r] = 0.f; accH[mbi][nb][r] = 0.f; }

    // prologue: W copies first (static data), then readiness spin (layer 1),
    // then A copies. mbar completes only when all PAIR_BYTES have landed.
    if (tid == 0) {
#pragma unroll
        for (int sp = 0; sp < 2; sp++) {
            const uint32_t m = mbF + 8 * sp;
            mbar_expect(m, PAIR_BYTES);
            bulkcp(sb + 40960 + sp * 10240,  Wzb + (size_t)(2 * sp) * WBLK_H, 10240, m);
            bulkcp(sb + 61440 + sp * 10240,  Whb + (size_t)(2 * sp) * WBLK_H, 10240, m);
        }
        if (layer == 1) {
            while (atomicAdd(&g_rdy[ry], 0) < 8) __nanosleep(64);
            __threadfence();
        }
#pragma unroll
        for (int sp = 0; sp < 2; sp++)
            bulkcp(sb + sp * 20480, Ab + (size_t)(2 * sp) * ABLK_H, 20480,
                   mbF + 8 * sp);
    }

    // mainloop: 8 pairs, 2 pair-slots
    for (int cg = 0; cg < 4; cg++) {
        const uint32_t ph = (uint32_t)(cg & 1);
#pragma unroll
        for (int sp = 0; sp < 2; sp++) {
            const int pr = cg * 2 + sp;
            mbar_wait(mbF + 8 * sp, ph);

#pragma unroll
            for (int hf = 0; hf < 2; hf++) {
                const int slot = 2 * sp + hf;
                const uint32_t aA = sb + slot * 10240 + aLane;
                const uint32_t bZ = sb + 40960 + slot * 5120 + bLane;
                const uint32_t bH = sb + 61440 + slot * 5120 + bLane;

#pragma unroll
                for (int ks = 0; ks < 2; ks++) {
                    const uint32_t kb = (uint32_t)(ks * 32);
                    uint32_t Af[2][4], zz[2][4], hh[2][4];
#pragma unroll
                    for (int mbi = 0; mbi < 2; mbi++)
                        ldsm4(Af[mbi], aA + mbi * (16 * 80) + kb);
#pragma unroll
                    for (int p = 0; p < 2; p++) {
                        ldsm4(zz[p], bZ + p * (16 * 80) + kb);
                        ldsm4(hh[p], bH + p * (16 * 80) + kb);
                    }
#pragma unroll
                    for (int p = 0; p < 2; p++)
#pragma unroll
                        for (int q = 0; q < 2; q++)
#pragma unroll
                            for (int mbi = 0; mbi < 2; mbi++) {
                                const int nb = 2 * p + q;
                                mma_f16(accZ[mbi][nb], Af[mbi], zz[p][2*q], zz[p][2*q+1]);
                                mma_f16(accH[mbi][nb], Af[mbi], hh[p][2*q], hh[p][2*q+1]);
                            }
                }
            }

            if (lane == 0) mbar_arrive(mbC + 8 * sp);

            if (tid == 0 && pr + 2 < 8) {
                mbar_wait(mbC + 8 * sp, ph);
                const int npr = pr + 2;
                const uint32_t m = mbF + 8 * sp;
                mbar_expect(m, PAIR_BYTES);
                bulkcp(sb + sp * 20480,         Ab  + (size_t)(2 * npr) * ABLK_H, 20480, m);
                bulkcp(sb + 40960 + sp * 10240, Wzb + (size_t)(2 * npr) * WBLK_H, 10240, m);
                bulkcp(sb + 61440 + sp * 10240, Whb + (size_t)(2 * npr) * WBLK_H, 10240, m);
            }
        }
    }

    // ============ activation in registers (before barrier): acc -> (a,b) ====
#pragma unroll
    for (int mbi = 0; mbi < 2; mbi++)
#pragma unroll
        for (int nb = 0; nb < 4; nb++) {
            const int col = 32 * wn + 8 * nb + 2 * tq;
            const float bzv0 = bz[colBase + col], bzv1 = bz[colBase + col + 1];
            const float bhv0 = bh[colBase + col], bhv1 = bh[colBase + col + 1];
#pragma unroll
            for (int hf = 0; hf < 2; hf++) {
                const float kv0 = accZ[mbi][nb][2 * hf]     + bzv0;
                const float kv1 = accZ[mbi][nb][2 * hf + 1] + bzv1;
                const float pv0 = accH[mbi][nb][2 * hf]     + bhv0;
                const float pv1 = accH[mbi][nb][2 * hf + 1] + bhv1;
                const float a0 = 1.0f / (1.0f + __expf(kv0));
                const float a1 = 1.0f / (1.0f + __expf(kv1));
                const float t0 = (pv0 >= 0.f) ? (pv0 + 0.5f) : (1.0f / (1.0f + __expf(-pv0)));
                const float t1 = (pv1 >= 0.f) ? (pv1 + 0.5f) : (1.0f / (1.0f + __expf(-pv1)));
                accZ[mbi][nb][2 * hf]     = a0;
                accZ[mbi][nb][2 * hf + 1] = a1;
                accH[mbi][nb][2 * hf]     = (1.0f - a0) * t0;
                accH[mbi][nb][2 * hf + 1] = (1.0f - a1) * t1;
            }
        }

    __syncthreads();   // stage buffers dead; reuse smem

    float2* pAB = (float2*)sm;            // 128 x 64, stride 66 float2
    float*  sA  = (float*)sm + 16896;     // 8 x 64
    float*  sB  = sA + 512;
    float*  hIn = sB + 512;

    // store (a,b) plane
#pragma unroll
    for (int mbi = 0; mbi < 2; mbi++)
#pragma unroll
        for (int nb = 0; nb < 4; nb++) {
            const int col = 32 * wn + 8 * nb + 2 * tq;
#pragma unroll
            for (int hf = 0; hf < 2; hf++) {
                const int row = 32 * wm + 16 * mbi + 8 * hf + gq;
                float2 v0; v0.x = accZ[mbi][nb][2 * hf];     v0.y = accH[mbi][nb][2 * hf];
                float2 v1; v1.x = accZ[mbi][nb][2 * hf + 1]; v1.y = accH[mbi][nb][2 * hf + 1];
                pAB[row * 66 + col    ] = v0;
                pAB[row * 66 + col + 1] = v1;
            }
        }
    __syncthreads();

    // chunk-local compose
#pragma unroll
    for (int k = 0; k < 2; k++) {
        const int item = tid + k * 256;
        const int j = item >> 6, cc = item & 63;
        float A = 1.f, Bv = 0.f;
#pragma unroll
        for (int t = 0; t < 16; t++) {
            float2 v = pAB[(j * 16 + t) * 66 + cc];
            Bv = fmaf(v.x, Bv, v.y);
            A *= v.x;
        }
        sA[j * 64 + cc] = A;
        sB[j * 64 + cc] = Bv;
    }
    __syncthreads();

    // CTA compose + publish loc
    if (tid < 64) {
        float A = 1.f, Bv = 0.f;
#pragma unroll
        for (int j = 0; j < 8; j++) {
            Bv = fmaf(sA[j * 64 + tid], Bv, sB[j * 64 + tid]);
            A *= sA[j * 64 + tid];
        }
        float2 pub; pub.x = A; pub.y = Bv;
        __stcg(&g_loc[layer][(size_t)ry * Hn + colBase + tid], pub);
        __threadfence();
    }
    __syncthreads();
    if (tid == 0) atomicExch(&g_fl[layer][ry * 8 + cx], 1);

    // lookback (batched compose, single sync per iteration via ping-pong)
    float hstart = 0.5f;
    if (ry != batchBase) {
        float alpha = 1.f, beta = 0.f;
        int p = ry - 1;
        int it = 0;
        for (;; it++) {
            const int slot = it & 1;
            if (tid < 32) {
                int rel = p - lane;
                int f = 0;
                if (rel >= batchBase) f = atomicAdd(&g_fl[layer][rel * 8 + cx], 0);
                unsigned m0 = __ballot_sync(0xffffffffu, f == 0);
                unsigned m2 = __ballot_sync(0xffffffffu, f == 2);
                int n = m0 ? (__ffs(m0) - 1) : 32;
                unsigned lim = (n >= 32) ? 0xffffffffu : ((1u << n) - 1u);
                unsigned m2v = m2 & lim;
                int f2 = m2v ? (__ffs(m2v) - 1) : -1;
                if (lane == 0) { s_n[slot] = n; s_f2[slot] = f2; }
            }
            __syncthreads();
            const int n = s_n[slot], f2 = s_f2[slot];

            if (f2 >= 0) {
                if (tid < 64) {
                    compose_n(layer, p, f2, colBase + tid, alpha, beta);
                    float iv = __ldcg(&g_inc[layer][(size_t)(p - f2) * Hn + colBase + tid]);
                    hstart = fmaf(alpha, iv, beta);
                }
                break;
            }
            if (tid < 64)
                compose_n(layer, p, n, colBase + tid, alpha, beta);
            p -= n;
            if (p < batchBase) {
                if (tid < 64) hstart = fmaf(alpha, 0.5f, beta);
                break;
            }
        }
    }

    // chunk entry states + publish inclusive
    if (tid < 64) {
        float h = hstart;
#pragma unroll
        for (int j = 0; j < 8; j++) {
            hIn[j * 64 + tid] = h;
            h = fmaf(sA[j * 64 + tid], h, sB[j * 64 + tid]);
        }
        __stcg(&g_inc[layer][(size_t)ry * Hn + colBase + tid], h);
        __threadfence();
        if ((ry & 31) == 31)
            finals[(ry >> 5) * Hn + colBase + tid] = h;
    }
    __syncthreads();
    if (tid == 0) atomicExch(&g_fl[layer][ry * 8 + cx], 2);

    // emit hidden states
#pragma unroll
    for (int k = 0; k < 2; k++) {
        const int item = tid + k * 256;
        const int j = item >> 6, cc = item & 63;
        float h = hIn[j * 64 + cc];
        if (layer == 0) {
            __half* dst = g_xh + (size_t)(ry * NCHUNK + 2 * cx + (cc >> 5)) * ABLK_H
                          + (cc & 31);
#pragma unroll
            for (int t = 0; t < 16; t++) {
                float2 v = pAB[(j * 16 + t) * 66 + cc];
                h = fmaf(v.x, h, v.y);
                dst[(j * 16 + t) * 40] = __float2half(h);
            }
        } else {
#pragma unroll
            for (int t = 0; t < 16; t++) {
                float2 v = pAB[(j * 16 + t) * 66 + cc];
                h = fmaf(v.x, h, v.y);
                __stcs(&out[(size_t)(rowBase + j * 16 + t) * Hn + colBase + cc], h);
            }
        }
    }

    // layer-0: signal this row tile's hidden block is ready for layer 1
    if (layer == 0) {
        __syncthreads();
        if (tid == 0) {
            __threadfence();
            atomicAdd(&g_rdy[ry], 1);
        }
    }
}

// --------------------------------- launch ----------------------------------
extern "C" void kernel_launch(void* const* d_in, const int* in_sizes, int n_in,
                              void* d_out, int out_size)
{
    const float* x   = (const float*)d_in[0];
    const float* wz0 = (const float*)d_in[1];
    const float* bz0 = (const float*)d_in[2];
    const float* wh0 = (const float*)d_in[3];
    const float* bh0 = (const float*)d_in[4];
    const float* wz1 = (const float*)d_in[5];
    const float* bz1 = (const float*)d_in[6];
    const float* wh1 = (const float*)d_in[7];
    const float* bh1 = (const float*)d_in[8];

    float* out    = (float*)d_out;
    float* finals = out + (size_t)Mtot * Hn;

    static int smem_set = 0;
    if (!smem_set) {
        cudaFuncSetAttribute(gemm_scan, cudaFuncAttributeMaxDynamicSharedMemorySize,
                             SMEM_BYTES);
        smem_set = 1;
    }

    setup_all<<<SETUP_BLOCKS, 256>>>(x, wz0, wh0, wz1, wh1);
    gemm_scan<<<2 * RYT * CXT, 256, SMEM_BYTES>>>(bz0, bh0, bz1, bh1, out, finals);
}

// round 17
// speedup vs baseline: 1.0268x; 1.0268x over previous
#include <cuda_runtime.h>
#include <cuda_fp16.h>
#include <math.h>
#include <stdint.h>

#define Bb 8
#define Ss 4096
#define Hn 512
#define Kd 512
#define Mtot (Bb*Ss)          // 32768
#define RYT 256               // row tiles (128 rows)
#define CXT 8                 // col tiles (64 cols)
#define NCHUNK 16             // K chunks of 32

// Tiled gmem images matching smem layout: 80B (40-half) padded rows.
#define ABLK_H 5120           // halves per (ry, chunk): 128 rows x 40
#define WBLK_H 2560           // halves per (mat, cx, chunk): 64 rows x 40

__device__ __align__(256) __half  g_x0[(size_t)RYT*NCHUNK*ABLK_H];
__device__ __align__(256) __half  g_xh[(size_t)RYT*NCHUNK*ABLK_H];
__device__ __align__(256) __half  g_w [(size_t)4*CXT*NCHUNK*WBLK_H];
__device__ __align__(256) float2  g_loc[2][RYT*Hn];
__device__ __align__(256) float   g_inc[2][RYT*Hn];
__device__ __align__(256) int     g_fl [2][RYT*CXT];
__device__ __align__(256) int     g_rdy[RYT];
__device__ int g_tick;

// ------------------------------ helpers ------------------------------------
__device__ __forceinline__ uint32_t s2u(const void* p) {
    uint32_t a;
    asm("{ .reg .u64 t; cvta.to.shared.u64 t, %1; cvt.u32.u64 %0, t; }"
        : "=r"(a) : "l"(p));
    return a;
}

__device__ __forceinline__ void mma_f16(float* d, const uint32_t* a,
                                        uint32_t b0, uint32_t b1) {
    asm volatile(
        "mma.sync.aligned.m16n8k16.row.col.f32.f16.f16.f32 "
        "{%0,%1,%2,%3}, {%4,%5,%6,%7}, {%8,%9}, {%0,%1,%2,%3};"
        : "+f"(d[0]), "+f"(d[1]), "+f"(d[2]), "+f"(d[3])
        : "r"(a[0]), "r"(a[1]), "r"(a[2]), "r"(a[3]), "r"(b0), "r"(b1));
}

__device__ __forceinline__ void ldsm4(uint32_t* r, uint32_t addr) {
    asm volatile("ldmatrix.sync.aligned.m8n8.x4.shared.b16 {%0,%1,%2,%3}, [%4];"
        : "=r"(r[0]), "=r"(r[1]), "=r"(r[2]), "=r"(r[3]) : "r"(addr));
}

__device__ __forceinline__ void mbar_init(uint32_t m, uint32_t cnt) {
    asm volatile("mbarrier.init.shared.b64 [%0], %1;" :: "r"(m), "r"(cnt) : "memory");
}
__device__ __forceinline__ void mbar_expect(uint32_t m, uint32_t bytes) {
    asm volatile("mbarrier.arrive.expect_tx.shared.b64 _, [%0], %1;"
                 :: "r"(m), "r"(bytes) : "memory");
}
__device__ __forceinline__ void mbar_arrive(uint32_t m) {
    asm volatile("mbarrier.arrive.shared.b64 _, [%0];" :: "r"(m) : "memory");
}
__device__ __forceinline__ void mbar_wait(uint32_t m, uint32_t parity) {
    asm volatile(
        "{\n\t.reg .pred P1;\n\t"
        "WL%=:\n\t"
        "mbarrier.try_wait.parity.acquire.cta.shared::cta.b64 P1, [%0], %1, 0x989680;\n\t"
        "@P1 bra.uni WD%=;\n\t"
        "bra.uni WL%=;\n\t"
        "WD%=:\n\t}"
        :: "r"(m), "r"(parity) : "memory");
}
__device__ __forceinline__ void bulkcp(uint32_t dst, const void* gsrc,
                                       uint32_t bytes, uint32_t mbar) {
    uint64_t ga;
    asm volatile("cvta.to.global.u64 %0, %1;" : "=l"(ga) : "l"(gsrc));
    asm volatile(
        "cp.async.bulk.shared::cluster.global.mbarrier::complete_tx::bytes "
        "[%0], [%1], %2, [%3];"
        :: "r"(dst), "l"(ga), "r"(bytes), "r"(mbar) : "memory");
}

// batched affine compose over predecessors pTop ... pTop-cnt+1
__device__ __forceinline__ void compose_n(int layer, int pTop, int cnt, int col,
                                          float& alpha, float& beta) {
    int l = 0;
    while (l + 8 <= cnt) {
        float2 buf[8];
#pragma unroll
        for (int j = 0; j < 8; j++)
            buf[j] = __ldcg(&g_loc[layer][(size_t)(pTop - l - j) * Hn + col]);
#pragma unroll
        for (int j = 0; j < 8; j++) {
            beta  = fmaf(alpha, buf[j].y, beta);
            alpha *= buf[j].x;
        }
        l += 8;
    }
    for (; l < cnt; l++) {
        float2 pv = __ldcg(&g_loc[layer][(size_t)(pTop - l) * Hn + col]);
        beta  = fmaf(alpha, pv.y, beta);
        alpha *= pv.x;
    }
}

// --------------------- merged setup: clear + conv x + conv w ----------------
#define CONVX_BLOCKS (Mtot*Kd/4/256)   // 16384
#define CONVW_BLOCKS (4*(Kd*Hn/4/256)) // 1024
#define CLR_BLOCKS 18
#define SETUP_BLOCKS (CONVX_BLOCKS + CONVW_BLOCKS + CLR_BLOCKS)

__global__ void setup_all(const float* __restrict__ x,
                          const float* __restrict__ w0, const float* __restrict__ w1,
                          const float* __restrict__ w2, const float* __restrict__ w3)
{
    const int bx = blockIdx.x;
    const int tid = threadIdx.x;

    if (bx < CONVX_BLOCKS) {
        int i = bx * 256 + tid;                   // over Mtot*Kd/4
        float4 v = ((const float4*)x)[i];
        __half2 p0 = __floats2half2_rn(v.x, v.y);
        __half2 p1 = __floats2half2_rn(v.z, v.w);
        const int m = i >> 7;
        const int k = (i & 127) * 4;
        const int ry = m >> 7, c = k >> 5, row = m & 127, col = k & 31;
        __half2* dst = (__half2*)&g_x0[(size_t)(ry * NCHUNK + c) * ABLK_H + row * 40 + col];
        dst[0] = p0; dst[1] = p1;
    } else if (bx < CONVX_BLOCKS + CONVW_BLOCKS) {
        const int b = bx - CONVX_BLOCKS;
        const float* srcs[4] = {w0, w1, w2, w3};
        const int mat = b >> 8;
        int i = (b & 255) * 256 + tid;            // over Kd*Hn/4
        float4 v = ((const float4*)srcs[mat])[i];
        __half2 p0 = __floats2half2_rn(v.x, v.y);
        __half2 p1 = __floats2half2_rn(v.z, v.w);
        const int h = i >> 7;
        const int k = (i & 127) * 4;
        const int cx = h >> 6, c = k >> 5, row = h & 63, col = k & 31;
        __half2* dst = (__half2*)&g_w[(size_t)(((mat * CXT + cx) * NCHUNK) + c) * WBLK_H
                                      + row * 40 + col];
        dst[0] = p0; dst[1] = p1;
    } else {
        int i = (bx - CONVX_BLOCKS - CONVW_BLOCKS) * 256 + tid;
        if (i < 2 * RYT * CXT) ((int*)g_fl)[i] = 0;
        else if (i < 2 * RYT * CXT + RYT) g_rdy[i - 2 * RYT * CXT] = 0;
        else if (i == 2 * RYT * CXT + RYT) g_tick = 0;
    }
}

// ---------------- fused dual GEMM + scan, BOTH layers in one kernel ---------
// smem: A slots 0..3 at 0 (4 x 10240), WZ slots at 40960 (4 x 5120),
// WH slots at 61440 (4 x 5120). Pipeline in PAIRS of chunks (2 pair-slots).
#define SMEM_BYTES 81920
#define PAIR_BYTES 40960

__global__ __launch_bounds__(256, 2)
void gemm_scan(const float* __restrict__ bz0, const float* __restrict__ bh0,
               const float* __restrict__ bz1, const float* __restrict__ bh1,
               float* __restrict__ out, float* __restrict__ finalsBase)
{
    extern __shared__ __align__(16) char sm[];
    const uint32_t sb = s2u(sm);
    __shared__ __align__(8) uint64_t s_full[2];
    __shared__ __align__(8) uint64_t s_cons[2];
    __shared__ int s_tick, s_n[2], s_f2[2];

    const int tid  = threadIdx.x;
    const int lane = tid & 31;
    const int wid  = tid >> 5;
    const int gq   = lane >> 2;
    const int tq   = lane & 3;
    const int wm   = wid & 3;
    const int wn   = wid >> 2;
    const uint32_t mbF = s2u(s_full);
    const uint32_t mbC = s2u(s_cons);

    if (tid == 0) {
        s_tick = atomicAdd(&g_tick, 1);
#pragma unroll
        for (int s = 0; s < 2; s++) {
            mbar_init(mbF + 8 * s, 1);
            mbar_init(mbC + 8 * s, 8);
        }
    }
    __syncthreads();
    const int tk    = s_tick;
    const int layer = (tk >= RYT * CXT) ? 1 : 0;
    const int tk2   = tk & (RYT * CXT - 1);
    const int ry = tk2 >> 3;
    const int cx = tk2 & 7;
    const int rowBase = ry * 128;
    const int colBase = cx * 64;
    const int batchBase = ry & ~31;

    const float* bz = layer ? bz1 : bz0;
    const float* bh = layer ? bh1 : bh0;
    float* finals = finalsBase + layer * Bb * Hn;

    const __half* Ab  = (layer ? g_xh : g_x0) + (size_t)ry * NCHUNK * ABLK_H;
    const __half* Wzb = g_w + (size_t)((2 * layer)     * CXT + cx) * NCHUNK * WBLK_H;
    const __half* Whb = g_w + (size_t)((2 * layer + 1) * CXT + cx) * NCHUNK * WBLK_H;

    const uint32_t aLane = (uint32_t)((32 * wm + (lane & 15)) * 80 + ((lane >> 4) << 4));
    const uint32_t bLane = (uint32_t)(((32 * wn) + ((lane >> 4) << 3) + (lane & 7)) * 80
                                      + (((lane >> 3) & 1) << 4));

    float accZ[2][4][4];
    float accH[2][4][4];
#pragma unroll
    for (int mbi = 0; mbi < 2; mbi++)
#pragma unroll
        for (int nb = 0; nb < 4; nb++)
#pragma unroll
            for (int r = 0; r < 4; r++) { accZ[mbi][nb][r] = 0.f; accH[mbi][nb][r] = 0.f; }

    // prologue: W copies first (static data), layer-1 readiness spin, then A.
    // mbar completes only when all PAIR_BYTES have landed.
    if (tid == 0) {
#pragma unroll
        for (int sp = 0; sp < 2; sp++) {
            const uint32_t m = mbF + 8 * sp;
            mbar_expect(m, PAIR_BYTES);
            bulkcp(sb + 40960 + sp * 10240,  Wzb + (size_t)(2 * sp) * WBLK_H, 10240, m);
            bulkcp(sb + 61440 + sp * 10240,  Whb + (size_t)(2 * sp) * WBLK_H, 10240, m);
        }
        if (layer == 1) {
            while (atomicAdd(&g_rdy[ry], 0) < 8) __nanosleep(64);
            __threadfence();
        }
#pragma unroll
        for (int sp = 0; sp < 2; sp++)
            bulkcp(sb + sp * 20480, Ab + (size_t)(2 * sp) * ABLK_H, 20480,
                   mbF + 8 * sp);
    }

    // mainloop: 8 pairs, 2 pair-slots, fully unrolled inner for immediates
    for (int cg = 0; cg < 4; cg++) {
        const uint32_t ph = (uint32_t)(cg & 1);
#pragma unroll
        for (int sp = 0; sp < 2; sp++) {
            const int pr = cg * 2 + sp;
            mbar_wait(mbF + 8 * sp, ph);

#pragma unroll
            for (int hf = 0; hf < 2; hf++) {
                const int slot = 2 * sp + hf;
                const uint32_t aA = sb + slot * 10240 + aLane;
                const uint32_t bZ = sb + 40960 + slot * 5120 + bLane;
                const uint32_t bH = sb + 61440 + slot * 5120 + bLane;

#pragma unroll
                for (int ks = 0; ks < 2; ks++) {
                    const uint32_t kb = (uint32_t)(ks * 32);
                    uint32_t Af[2][4], zz[2][4], hh[2][4];
#pragma unroll
                    for (int mbi = 0; mbi < 2; mbi++)
                        ldsm4(Af[mbi], aA + mbi * (16 * 80) + kb);
#pragma unroll
                    for (int p = 0; p < 2; p++) {
                        ldsm4(zz[p], bZ + p * (16 * 80) + kb);
                        ldsm4(hh[p], bH + p * (16 * 80) + kb);
                    }
#pragma unroll
                    for (int p = 0; p < 2; p++)
#pragma unroll
                        for (int q = 0; q < 2; q++)
#pragma unroll
                            for (int mbi = 0; mbi < 2; mbi++) {
                                const int nb = 2 * p + q;
                                mma_f16(accZ[mbi][nb], Af[mbi], zz[p][2*q], zz[p][2*q+1]);
                                mma_f16(accH[mbi][nb], Af[mbi], hh[p][2*q], hh[p][2*q+1]);
                            }
                }
            }

            if (lane == 0) mbar_arrive(mbC + 8 * sp);

            if (tid == 0 && pr + 2 < 8) {
                mbar_wait(mbC + 8 * sp, ph);
                const int npr = pr + 2;
                const uint32_t m = mbF + 8 * sp;
                mbar_expect(m, PAIR_BYTES);
                bulkcp(sb + sp * 20480,         Ab  + (size_t)(2 * npr) * ABLK_H, 20480, m);
                bulkcp(sb + 40960 + sp * 10240, Wzb + (size_t)(2 * npr) * WBLK_H, 10240, m);
                bulkcp(sb + 61440 + sp * 10240, Whb + (size_t)(2 * npr) * WBLK_H, 10240, m);
            }
        }
    }

    // ==================== epilogue: activation + fused scan =================
    __syncthreads();

    float* aP  = (float*)sm;          // 128 x 64, stride 68
    float* bP  = aP + 8704;
    float* sA  = bP + 8704;           // 8 x 64
    float* sB  = sA + 512;
    float* hIn = sB + 512;

#pragma unroll
    for (int mbi = 0; mbi < 2; mbi++)
#pragma unroll
        for (int nb = 0; nb < 4; nb++) {
            const int col = 32 * wn + 8 * nb + 2 * tq;
            const float bzv0 = bz[colBase + col], bzv1 = bz[colBase + col + 1];
            const float bhv0 = bh[colBase + col], bhv1 = bh[colBase + col + 1];
#pragma unroll
            for (int hf = 0; hf < 2; hf++) {
                const int row = 32 * wm + 16 * mbi + 8 * hf + gq;
                const float kv0 = accZ[mbi][nb][2 * hf]     + bzv0;
                const float kv1 = accZ[mbi][nb][2 * hf + 1] + bzv1;
                const float pv0 = accH[mbi][nb][2 * hf]     + bhv0;
                const float pv1 = accH[mbi][nb][2 * hf + 1] + bhv1;
                const float a0 = 1.0f / (1.0f + __expf(kv0));
                const float a1 = 1.0f / (1.0f + __expf(kv1));
                const float z0 = 1.0f - a0;
                const float z1 = 1.0f - a1;
                const float t0 = (pv0 >= 0.f) ? (pv0 + 0.5f) : (1.0f / (1.0f + __expf(-pv0)));
                const float t1 = (pv1 >= 0.f) ? (pv1 + 0.5f) : (1.0f / (1.0f + __expf(-pv1)));
                aP[row * 68 + col    ] = a0;
                aP[row * 68 + col + 1] = a1;
                bP[row * 68 + col    ] = z0 * t0;
                bP[row * 68 + col + 1] = z1 * t1;
            }
        }
    __syncthreads();

    // chunk-local compose
#pragma unroll
    for (int k = 0; k < 2; k++) {
        const int item = tid + k * 256;
        const int j = item >> 6, cc = item & 63;
        float A = 1.f, Bv = 0.f;
#pragma unroll
        for (int t = 0; t < 16; t++) {
            const int row = j * 16 + t;
            const float a = aP[row * 68 + cc];
            const float b = bP[row * 68 + cc];
            Bv = fmaf(a, Bv, b);
            A *= a;
        }
        sA[j * 64 + cc] = A;
        sB[j * 64 + cc] = Bv;
    }
    __syncthreads();

    // CTA compose + publish loc
    if (tid < 64) {
        float A = 1.f, Bv = 0.f;
#pragma unroll
        for (int j = 0; j < 8; j++) {
            Bv = fmaf(sA[j * 64 + tid], Bv, sB[j * 64 + tid]);
            A *= sA[j * 64 + tid];
        }
        float2 pub; pub.x = A; pub.y = Bv;
        __stcg(&g_loc[layer][(size_t)ry * Hn + colBase + tid], pub);
        __threadfence();
    }
    __syncthreads();
    if (tid == 0) atomicExch(&g_fl[layer][ry * 8 + cx], 1);

    // lookback (batched compose, single sync per iteration via ping-pong)
    float hstart = 0.5f;
    if (ry != batchBase) {
        float alpha = 1.f, beta = 0.f;
        int p = ry - 1;
        int it = 0;
        for (;; it++) {
            const int slot = it & 1;
            if (tid < 32) {
                int rel = p - lane;
                int f = 0;
                if (rel >= batchBase) f = atomicAdd(&g_fl[layer][rel * 8 + cx], 0);
                unsigned m0 = __ballot_sync(0xffffffffu, f == 0);
                unsigned m2 = __ballot_sync(0xffffffffu, f == 2);
                int n = m0 ? (__ffs(m0) - 1) : 32;
                unsigned lim = (n >= 32) ? 0xffffffffu : ((1u << n) - 1u);
                unsigned m2v = m2 & lim;
                int f2 = m2v ? (__ffs(m2v) - 1) : -1;
                if (lane == 0) { s_n[slot] = n; s_f2[slot] = f2; }
            }
            __syncthreads();
            const int n = s_n[slot], f2 = s_f2[slot];

            if (f2 >= 0) {
                if (tid < 64) {
                    compose_n(layer, p, f2, colBase + tid, alpha, beta);
                    float iv = __ldcg(&g_inc[layer][(size_t)(p - f2) * Hn + colBase + tid]);
                    hstart = fmaf(alpha, iv, beta);
                }
                break;
            }
            if (tid < 64)
                compose_n(layer, p, n, colBase + tid, alpha, beta);
            p -= n;
            if (p < batchBase) {
                if (tid < 64) hstart = fmaf(alpha, 0.5f, beta);
                break;
            }
        }
    }

    // chunk entry states + publish inclusive
    if (tid < 64) {
        float h = hstart;
#pragma unroll
        for (int j = 0; j < 8; j++) {
            hIn[j * 64 + tid] = h;
            h = fmaf(sA[j * 64 + tid], h, sB[j * 64 + tid]);
        }
        __stcg(&g_inc[layer][(size_t)ry * Hn + colBase + tid], h);
        __threadfence();
        if ((ry & 31) == 31)
            finals[(ry >> 5) * Hn + colBase + tid] = h;
    }
    __syncthreads();
    if (tid == 0) atomicExch(&g_fl[layer][ry * 8 + cx], 2);

    // emit hidden states
#pragma unroll
    for (int k = 0; k < 2; k++) {
        const int item = tid + k * 256;
        const int j = item >> 6, cc = item & 63;
        float h = hIn[j * 64 + cc];
        if (layer == 0) {
            __half* dst = g_xh + (size_t)(ry * NCHUNK + 2 * cx + (cc >> 5)) * ABLK_H
                          + (cc & 31);
#pragma unroll
            for (int t = 0; t < 16; t++) {
                const int row = j * 16 + t;
                h = fmaf(aP[row * 68 + cc], h, bP[row * 68 + cc]);
                dst[row * 40] = __float2half(h);
            }
        } else {
#pragma unroll
            for (int t = 0; t < 16; t++) {
                const int row = j * 16 + t;
                h = fmaf(aP[row * 68 + cc], h, bP[row * 68 + cc]);
                __stcs(&out[(size_t)(rowBase + row) * Hn + colBase + cc], h);
            }
        }
    }

    // layer-0: signal this row tile's hidden block is ready for layer 1
    if (layer == 0) {
        __syncthreads();
        if (tid == 0) {
            __threadfence();
            atomicAdd(&g_rdy[ry], 1);
        }
    }
}

// --------------------------------- launch ----------------------------------
extern "C" void kernel_launch(void* const* d_in, const int* in_sizes, int n_in,
                              void* d_out, int out_size)
{
    const float* x   = (const float*)d_in[0];
    const float* wz0 = (const float*)d_in[1];
    const float* bz0 = (const float*)d_in[2];
    const float* wh0 = (const float*)d_in[3];
    const float* bh0 = (const float*)d_in[4];
    const float* wz1 = (const float*)d_in[5];
    const float* bz1 = (const float*)d_in[6];
    const float* wh1 = (const float*)d_in[7];
    const float* bh1 = (const float*)d_in[8];

    float* out    = (float*)d_out;
    float* finals = out + (size_t)Mtot * Hn;

    static int smem_set = 0;
    if (!smem_set) {
        cudaFuncSetAttribute(gemm_scan, cudaFuncAttributeMaxDynamicSharedMemorySize,
                             SMEM_BYTES);
        smem_set = 1;
    }

    setup_all<<<SETUP_BLOCKS, 256>>>(x, wz0, wh0, wz1, wh1);
    gemm_scan<<<2 * RYT * CXT, 256, SMEM_BYTES>>>(bz0, bh0, bz1, bh1, out, finals);
}